// round 5
// baseline (speedup 1.0000x reference)
#include <cuda_runtime.h>

// VLAD pooling: x [32,4096,128] f32, centroids [64,128] f32 -> out [32, 8192] f32
//
// Pipeline (3 kernels on default stream, graph-capturable, no allocations):
//   1) vlad_zero      : zero __device__ scratch (g_vlad, g_asum)
//   2) vlad_main      : per-64-point tiles: GEMM1 dots -> dist -> softmax ->
//                       GEMM2 accumulation into register vlad tiles -> atomicAdd
//   3) vlad_finalize  : vlad -= asum*c, L2-normalize per batch, write d_out

#define B_      32
#define N_      4096
#define D_      128
#define K_      64
#define ALPHA_  100.0f
#define TILE_   64
#define SPLITS_ 8
#define PTSB_   (N_ / SPLITS_)     // 512 points per block
#define TILESB_ (PTSB_ / TILE_)    // 8 tiles per block

// shared memory layout (floats)
#define SM_CS 0                    // centroids [64][128]
#define SM_C2 8192                 // c2 [64]
#define SM_XS 8256                 // x tile [64][128], XOR-swizzled by (n&7) on float4 column
#define SM_X2 16448                // x2 [64]
#define SM_AS 16512                // logits/weights [64][72]  (stride 72 avoids bank aliasing)
#define A_STRIDE 72
#define SMEM_FLOATS (SM_AS + TILE_ * A_STRIDE)   // 21120 floats = 84480 B

__device__ float g_vlad[B_ * K_ * D_];
__device__ float g_asum[B_ * K_];

__global__ void vlad_zero() {
    int stride = gridDim.x * blockDim.x;
    for (int i = blockIdx.x * blockDim.x + threadIdx.x; i < B_ * K_ * D_; i += stride)
        g_vlad[i] = 0.f;
    for (int i = blockIdx.x * blockDim.x + threadIdx.x; i < B_ * K_; i += stride)
        g_asum[i] = 0.f;
}

__device__ __forceinline__ float dot4acc(float4 a, float4 b, float acc) {
    return fmaf(a.x, b.x, fmaf(a.y, b.y, fmaf(a.z, b.z, fmaf(a.w, b.w, acc))));
}

__global__ __launch_bounds__(256, 2)
void vlad_main(const float* __restrict__ x, const float* __restrict__ cent) {
    extern __shared__ float sm[];
    float* cs = sm + SM_CS;
    float* c2 = sm + SM_C2;
    float* xs = sm + SM_XS;
    float* x2 = sm + SM_X2;
    float* aw = sm + SM_AS;

    const int tid  = threadIdx.x;
    const int b    = blockIdx.y;
    const int s    = blockIdx.x;
    const int q    = tid & 3;      // quarter of a row for gmem loads
    const int r    = tid >> 2;     // row (point) for gmem loads, 0..63
    const int tn   = tid & 15;     // GEMM1 n-group / GEMM2 d-group
    const int tkg  = tid >> 4;     // k-group, 0..15
    const int k0   = tkg * 4;
    const int warp = tid >> 5;
    const int lane = tid & 31;

    // ---- load centroids into smem (unswizzled) + c2 ----
    {
        const float4* c4 = (const float4*)cent;
        float csum = 0.f;
        #pragma unroll
        for (int it = 0; it < 8; ++it) {
            int f4 = q + it * 4;
            float4 v = c4[r * 32 + f4];
            ((float4*)(cs + r * 128))[f4] = v;
            csum = dot4acc(v, v, csum);
        }
        csum += __shfl_xor_sync(0xffffffffu, csum, 1);
        csum += __shfl_xor_sync(0xffffffffu, csum, 2);
        if (q == 0) c2[r] = csum;
    }

    // persistent register accumulators: vlad micro-tile [4k][8d], asum[4k]
    float vl[4][8];
    #pragma unroll
    for (int j = 0; j < 4; ++j)
        #pragma unroll
        for (int d = 0; d < 8; ++d) vl[j][d] = 0.f;
    float asum[4] = {0.f, 0.f, 0.f, 0.f};

    for (int t = 0; t < TILESB_; ++t) {
        __syncthreads();  // previous tile's GEMM2 reads done (and centroid stores on t==0)

        // ---- load x tile (XOR-swizzled by point&7 on float4 column) + x2 ----
        {
            const int rowg = b * N_ + s * PTSB_ + t * TILE_ + r;
            const float4* x4 = (const float4*)x;
            float xsum = 0.f;
            #pragma unroll
            for (int it = 0; it < 8; ++it) {
                int f4 = q + it * 4;
                float4 v = x4[rowg * 32 + f4];
                ((float4*)(xs + r * 128))[f4 ^ (r & 7)] = v;
                xsum = dot4acc(v, v, xsum);
            }
            xsum += __shfl_xor_sync(0xffffffffu, xsum, 1);
            xsum += __shfl_xor_sync(0xffffffffu, xsum, 2);
            if (q == 0) x2[r] = xsum;
        }
        __syncthreads();

        // ---- GEMM1: dots for points {tn, tn+16, tn+32, tn+48} x clusters {k0..k0+3} ----
        // (n strided by 16 so the 16 lanes of a warp hit 16 consecutive rows ->
        //  swizzled columns span 8 bank groups -> conflict-free 2-cycle LDS.128)
        float acc[4][4];
        #pragma unroll
        for (int i = 0; i < 4; ++i)
            #pragma unroll
            for (int j = 0; j < 4; ++j) acc[i][j] = 0.f;

        const int swn = tn & 7;  // (tn + 16*i) & 7 == tn & 7
        #pragma unroll 4
        for (int d4 = 0; d4 < 32; ++d4) {
            float4 xv[4], cv[4];
            #pragma unroll
            for (int i = 0; i < 4; ++i)
                xv[i] = ((const float4*)(xs + (tn + 16 * i) * 128))[d4 ^ swn];
            #pragma unroll
            for (int j = 0; j < 4; ++j)
                cv[j] = ((const float4*)(cs + (k0 + j) * 128))[d4];
            #pragma unroll
            for (int i = 0; i < 4; ++i)
                #pragma unroll
                for (int j = 0; j < 4; ++j)
                    acc[i][j] = dot4acc(xv[i], cv[j], acc[i][j]);
        }

        // ---- logits = -ALPHA * sqrt(max(x2 + c2 - 2*dot, 0)) ----
        #pragma unroll
        for (int i = 0; i < 4; ++i) {
            const int n = tn + 16 * i;
            const float xx = x2[n];
            float4 lg;
            {
                float d2 = fmaxf(xx + c2[k0 + 0] - 2.f * acc[i][0], 0.f);
                lg.x = -ALPHA_ * sqrtf(d2);
                d2 = fmaxf(xx + c2[k0 + 1] - 2.f * acc[i][1], 0.f);
                lg.y = -ALPHA_ * sqrtf(d2);
                d2 = fmaxf(xx + c2[k0 + 2] - 2.f * acc[i][2], 0.f);
                lg.z = -ALPHA_ * sqrtf(d2);
                d2 = fmaxf(xx + c2[k0 + 3] - 2.f * acc[i][3], 0.f);
                lg.w = -ALPHA_ * sqrtf(d2);
            }
            *(float4*)(aw + n * A_STRIDE + k0) = lg;
        }
        __syncthreads();

        // ---- softmax over K=64 per point, one warp handles 8 points ----
        #pragma unroll
        for (int p = 0; p < 8; ++p) {
            const int n = warp * 8 + p;
            float2 v = *(const float2*)(aw + n * A_STRIDE + lane * 2);
            float m = fmaxf(v.x, v.y);
            #pragma unroll
            for (int o = 16; o > 0; o >>= 1)
                m = fmaxf(m, __shfl_xor_sync(0xffffffffu, m, o));
            float e0 = __expf(v.x - m);
            float e1 = __expf(v.y - m);
            float ssum = e0 + e1;
            #pragma unroll
            for (int o = 16; o > 0; o >>= 1)
                ssum += __shfl_xor_sync(0xffffffffu, ssum, o);
            float inv = 1.0f / ssum;
            *(float2*)(aw + n * A_STRIDE + lane * 2) = make_float2(e0 * inv, e1 * inv);
        }
        __syncthreads();

        // ---- GEMM2: vl[k0..k0+3][8d @ d0=tn*8] += sum_n a[n][k] * x[n][d] ----
        #pragma unroll 4
        for (int n = 0; n < TILE_; ++n) {
            float4 av = *(const float4*)(aw + n * A_STRIDE + k0);
            const float4* xrow = (const float4*)(xs + n * 128);
            const int swz = n & 7;
            float4 xa = xrow[(2 * tn) ^ swz];       // logical d4 = 2*tn
            float4 xb = xrow[(2 * tn + 1) ^ swz];   // logical d4 = 2*tn+1
            const float wv[4]  = {av.x, av.y, av.z, av.w};
            const float xvv[8] = {xa.x, xa.y, xa.z, xa.w, xb.x, xb.y, xb.z, xb.w};
            #pragma unroll
            for (int j = 0; j < 4; ++j)
                #pragma unroll
                for (int d = 0; d < 8; ++d)
                    vl[j][d] = fmaf(wv[j], xvv[d], vl[j][d]);
            if (tn == 0) {
                asum[0] += av.x; asum[1] += av.y; asum[2] += av.z; asum[3] += av.w;
            }
        }
    }

    // ---- flush register accumulators (8 blocks/batch contend -> atomics) ----
    const int base = b * K_ * D_;
    #pragma unroll
    for (int j = 0; j < 4; ++j)
        #pragma unroll
        for (int d = 0; d < 8; ++d)
            atomicAdd(&g_vlad[base + (k0 + j) * D_ + tn * 8 + d], vl[j][d]);
    if (tn == 0) {
        #pragma unroll
        for (int j = 0; j < 4; ++j)
            atomicAdd(&g_asum[b * K_ + k0 + j], asum[j]);
    }
}

__global__ __launch_bounds__(256)
void vlad_finalize(const float* __restrict__ cent, float* __restrict__ out) {
    const int b = blockIdx.x;
    const int tid = threadIdx.x;
    float v[32];
    float ssq = 0.f;
    #pragma unroll
    for (int m = 0; m < 32; ++m) {
        const int e = m * 256 + tid;
        const int k = e >> 7;
        const int d = e & 127;
        float val = fmaf(-g_asum[b * K_ + k], cent[k * D_ + d], g_vlad[b * K_ * D_ + e]);
        v[m] = val;
        ssq = fmaf(val, val, ssq);
    }
    #pragma unroll
    for (int o = 16; o > 0; o >>= 1)
        ssq += __shfl_xor_sync(0xffffffffu, ssq, o);

    __shared__ float red[8];
    __shared__ float s_inv;
    if ((tid & 31) == 0) red[tid >> 5] = ssq;
    __syncthreads();
    if (tid == 0) {
        float tot = 0.f;
        #pragma unroll
        for (int w = 0; w < 8; ++w) tot += red[w];
        float nrm = fmaxf(sqrtf(tot), 1e-12f);
        s_inv = 1.0f / nrm;
    }
    __syncthreads();
    const float inv = s_inv;
    #pragma unroll
    for (int m = 0; m < 32; ++m)
        out[b * K_ * D_ + m * 256 + tid] = v[m] * inv;
}

extern "C" void kernel_launch(void* const* d_in, const int* in_sizes, int n_in,
                              void* d_out, int out_size) {
    const float* x    = (const float*)d_in[0];   // [32,4096,128] f32
    const float* cent = (const float*)d_in[1];   // [64,128] f32
    float* out = (float*)d_out;                  // [32,8192] f32
    (void)in_sizes; (void)n_in; (void)out_size;

    cudaFuncSetAttribute(vlad_main, cudaFuncAttributeMaxDynamicSharedMemorySize,
                         SMEM_FLOATS * (int)sizeof(float));

    vlad_zero<<<64, 256>>>();
    dim3 grid(SPLITS_, B_);
    vlad_main<<<grid, 256, SMEM_FLOATS * sizeof(float)>>>(x, cent);
    vlad_finalize<<<B_, 256>>>(cent, out);
}

// round 6
// speedup vs baseline: 1.1605x; 1.1605x over previous
#include <cuda_runtime.h>

// VLAD pooling: x [32,4096,128] f32, centroids [64,128] f32 -> out [32, 8192] f32
//
// R6: packed fma.rn.f32x2 for both GEMMs (halves FFMA instruction count on the
//     dual-rate fp32 path) + flat 296-CTA chunked tile assignment (perfect
//     2-CTA/SM balance, flush-on-batch-change for register accumulators).

#define B_      32
#define N_      4096
#define D_      128
#define K_      64
#define ALPHA_  100.0f
#define TILE_   64
#define NTILES_ (B_ * (N_ / TILE_))   // 2048 tiles total
#define NCTA_   296                   // 148 SMs * 2 CTAs
#define BASE_T  (NTILES_ / NCTA_)     // 6
#define EXTRA_T (NTILES_ - NCTA_ * BASE_T)  // 272

// shared memory layout (floats)
#define SM_CS 0                    // centroids [64][128]
#define SM_C2 8192                 // c2 [64]
#define SM_XS 8256                 // x tile [64][128], XOR-swizzled by (n&7) on float4 column
#define SM_X2 16448                // x2 [64]
#define SM_AS 16512                // logits/weights [64][72] (stride 72 avoids bank aliasing)
#define A_STRIDE 72
#define SMEM_FLOATS (SM_AS + TILE_ * A_STRIDE)   // 21120 floats = 84480 B

__device__ float g_vlad[B_ * K_ * D_];
__device__ float g_asum[B_ * K_];

typedef unsigned long long u64t;

__device__ __forceinline__ u64t pk2(float lo, float hi) {
    u64t r; asm("mov.b64 %0, {%1,%2};" : "=l"(r) : "f"(lo), "f"(hi)); return r;
}
__device__ __forceinline__ void upk2(u64t v, float& lo, float& hi) {
    asm("mov.b64 {%0,%1}, %2;" : "=f"(lo), "=f"(hi) : "l"(v));
}
__device__ __forceinline__ u64t fma2(u64t a, u64t b, u64t c) {
    u64t d; asm("fma.rn.f32x2 %0, %1, %2, %3;" : "=l"(d) : "l"(a), "l"(b), "l"(c)); return d;
}

__global__ void vlad_zero() {
    int i = blockIdx.x * blockDim.x + threadIdx.x;
    if (i < B_ * K_ * D_) g_vlad[i] = 0.f;
    if (i < B_ * K_) g_asum[i] = 0.f;
}

__device__ __forceinline__ float dot4acc(float4 a, float4 b, float acc) {
    return fmaf(a.x, b.x, fmaf(a.y, b.y, fmaf(a.z, b.z, fmaf(a.w, b.w, acc))));
}

__global__ __launch_bounds__(256, 2)
void vlad_main(const float* __restrict__ x, const float* __restrict__ cent) {
    extern __shared__ float sm[];
    float* cs = sm + SM_CS;
    float* c2 = sm + SM_C2;
    float* xs = sm + SM_XS;
    float* x2 = sm + SM_X2;
    float* aw = sm + SM_AS;

    const int tid  = threadIdx.x;
    const int cta  = blockIdx.x;
    const int q    = tid & 3;      // quarter of a row for gmem loads
    const int r    = tid >> 2;     // row (point) for gmem loads, 0..63
    const int tn   = tid & 15;     // GEMM1 n-group / GEMM2 d-group
    const int tkg  = tid >> 4;     // k-group, 0..15
    const int k0   = tkg * 4;
    const int warp = tid >> 5;
    const int lane = tid & 31;

    // chunked contiguous tile range for this CTA
    const int start = cta * BASE_T + (cta < EXTRA_T ? cta : EXTRA_T);
    const int cnt   = BASE_T + (cta < EXTRA_T ? 1 : 0);

    // ---- load centroids into smem (unswizzled) + c2 ----
    {
        const float4* c4 = (const float4*)cent;
        float csum = 0.f;
        #pragma unroll
        for (int it = 0; it < 8; ++it) {
            int f4 = q + it * 4;
            float4 v = c4[r * 32 + f4];
            ((float4*)(cs + r * 128))[f4] = v;
            csum = dot4acc(v, v, csum);
        }
        csum += __shfl_xor_sync(0xffffffffu, csum, 1);
        csum += __shfl_xor_sync(0xffffffffu, csum, 2);
        if (q == 0) c2[r] = csum;
    }

    // persistent register accumulators: vlad micro-tile [4k][4 d-pairs], asum[4k]
    u64t vl2[4][4];
    #pragma unroll
    for (int j = 0; j < 4; ++j)
        #pragma unroll
        for (int p = 0; p < 4; ++p) vl2[j][p] = 0ull;
    float asum[4] = {0.f, 0.f, 0.f, 0.f};
    int cur_b = start >> 6;  // 64 tiles per batch

    for (int it = 0; it < cnt; ++it) {
        const int tg = start + it;
        const int b  = tg >> 6;
        const int t  = tg & 63;

        if (b != cur_b) {
            // batch changed mid-chunk: flush register accumulators (regs+atomics only)
            const int base = cur_b * K_ * D_;
            #pragma unroll
            for (int j = 0; j < 4; ++j)
                #pragma unroll
                for (int p = 0; p < 4; ++p) {
                    float lo, hi; upk2(vl2[j][p], lo, hi);
                    atomicAdd(&g_vlad[base + (k0 + j) * D_ + tn * 8 + 2 * p], lo);
                    atomicAdd(&g_vlad[base + (k0 + j) * D_ + tn * 8 + 2 * p + 1], hi);
                    vl2[j][p] = 0ull;
                }
            if (tn == 0) {
                #pragma unroll
                for (int j = 0; j < 4; ++j) {
                    atomicAdd(&g_asum[cur_b * K_ + k0 + j], asum[j]);
                    asum[j] = 0.f;
                }
            }
            cur_b = b;
        }

        __syncthreads();  // previous tile's GEMM2 reads done (and centroid stores on it==0)

        // ---- load x tile (XOR-swizzled by point&7 on float4 column) + x2 ----
        {
            const int rowg = b * N_ + t * TILE_ + r;
            const float4* x4 = (const float4*)x;
            float xsum = 0.f;
            #pragma unroll
            for (int i8 = 0; i8 < 8; ++i8) {
                int f4 = q + i8 * 4;
                float4 v = x4[rowg * 32 + f4];
                ((float4*)(xs + r * 128))[f4 ^ (r & 7)] = v;
                xsum = dot4acc(v, v, xsum);
            }
            xsum += __shfl_xor_sync(0xffffffffu, xsum, 1);
            xsum += __shfl_xor_sync(0xffffffffu, xsum, 2);
            if (q == 0) x2[r] = xsum;
        }
        __syncthreads();

        // ---- GEMM1 (f32x2): dots for points {tn,tn+16,tn+32,tn+48} x clusters {k0..k0+3} ----
        // acc2[i][j] holds (even-d partial, odd-d partial); reduced after the loop.
        u64t acc2[4][4];
        #pragma unroll
        for (int i = 0; i < 4; ++i)
            #pragma unroll
            for (int j = 0; j < 4; ++j) acc2[i][j] = 0ull;

        const int swn = tn & 7;
        #pragma unroll 4
        for (int d4 = 0; d4 < 32; ++d4) {
            ulonglong2 xv[4], cv[4];
            #pragma unroll
            for (int i = 0; i < 4; ++i)
                xv[i] = ((const ulonglong2*)(xs + (tn + 16 * i) * 128))[d4 ^ swn];
            #pragma unroll
            for (int j = 0; j < 4; ++j)
                cv[j] = ((const ulonglong2*)(cs + (k0 + j) * 128))[d4];
            #pragma unroll
            for (int i = 0; i < 4; ++i)
                #pragma unroll
                for (int j = 0; j < 4; ++j) {
                    acc2[i][j] = fma2(xv[i].x, cv[j].x, acc2[i][j]);
                    acc2[i][j] = fma2(xv[i].y, cv[j].y, acc2[i][j]);
                }
        }

        // ---- logits = -ALPHA * sqrt(max(x2 + c2 - 2*dot, 0)) ----
        #pragma unroll
        for (int i = 0; i < 4; ++i) {
            const int n = tn + 16 * i;
            const float xx = x2[n];
            float4 lg;
            #pragma unroll
            for (int j = 0; j < 4; ++j) {
                float lo, hi; upk2(acc2[i][j], lo, hi);
                float dot = lo + hi;
                float d2 = fmaxf(xx + c2[k0 + j] - 2.f * dot, 0.f);
                ((float*)&lg)[j] = -ALPHA_ * sqrtf(d2);
            }
            *(float4*)(aw + n * A_STRIDE + k0) = lg;
        }
        __syncthreads();

        // ---- softmax over K=64 per point, one warp handles 8 points ----
        #pragma unroll
        for (int p = 0; p < 8; ++p) {
            const int n = warp * 8 + p;
            float2 v = *(const float2*)(aw + n * A_STRIDE + lane * 2);
            float m = fmaxf(v.x, v.y);
            #pragma unroll
            for (int o = 16; o > 0; o >>= 1)
                m = fmaxf(m, __shfl_xor_sync(0xffffffffu, m, o));
            float e0 = __expf(v.x - m);
            float e1 = __expf(v.y - m);
            float ssum = e0 + e1;
            #pragma unroll
            for (int o = 16; o > 0; o >>= 1)
                ssum += __shfl_xor_sync(0xffffffffu, ssum, o);
            float inv = 1.0f / ssum;
            *(float2*)(aw + n * A_STRIDE + lane * 2) = make_float2(e0 * inv, e1 * inv);
        }
        __syncthreads();

        // ---- GEMM2 (f32x2): vl2[k0..k0+3][4 d-pairs @ d0=tn*8] += a[n][k] * x[n][d] ----
        #pragma unroll 4
        for (int n = 0; n < TILE_; ++n) {
            float4 av = *(const float4*)(aw + n * A_STRIDE + k0);
            const ulonglong2* xrow = (const ulonglong2*)(xs + n * 128);
            const int swz = n & 7;
            ulonglong2 xa = xrow[(2 * tn) ^ swz];       // logical d4 = 2*tn
            ulonglong2 xb = xrow[(2 * tn + 1) ^ swz];   // logical d4 = 2*tn+1
            u64t xp[4] = {xa.x, xa.y, xb.x, xb.y};
            u64t w2[4] = {pk2(av.x, av.x), pk2(av.y, av.y),
                          pk2(av.z, av.z), pk2(av.w, av.w)};
            #pragma unroll
            for (int j = 0; j < 4; ++j)
                #pragma unroll
                for (int p = 0; p < 4; ++p)
                    vl2[j][p] = fma2(w2[j], xp[p], vl2[j][p]);
            if (tn == 0) {
                asum[0] += av.x; asum[1] += av.y; asum[2] += av.z; asum[3] += av.w;
            }
        }
    }

    // ---- final flush of register accumulators ----
    const int base = cur_b * K_ * D_;
    #pragma unroll
    for (int j = 0; j < 4; ++j)
        #pragma unroll
        for (int p = 0; p < 4; ++p) {
            float lo, hi; upk2(vl2[j][p], lo, hi);
            atomicAdd(&g_vlad[base + (k0 + j) * D_ + tn * 8 + 2 * p], lo);
            atomicAdd(&g_vlad[base + (k0 + j) * D_ + tn * 8 + 2 * p + 1], hi);
        }
    if (tn == 0) {
        #pragma unroll
        for (int j = 0; j < 4; ++j)
            atomicAdd(&g_asum[cur_b * K_ + k0 + j], asum[j]);
    }
}

__global__ __launch_bounds__(256)
void vlad_finalize(const float* __restrict__ cent, float* __restrict__ out) {
    const int b = blockIdx.x;
    const int tid = threadIdx.x;
    float v[32];
    float ssq = 0.f;
    #pragma unroll
    for (int m = 0; m < 32; ++m) {
        const int e = m * 256 + tid;
        const int k = e >> 7;
        const int d = e & 127;
        float val = fmaf(-g_asum[b * K_ + k], cent[k * D_ + d], g_vlad[b * K_ * D_ + e]);
        v[m] = val;
        ssq = fmaf(val, val, ssq);
    }
    #pragma unroll
    for (int o = 16; o > 0; o >>= 1)
        ssq += __shfl_xor_sync(0xffffffffu, ssq, o);

    __shared__ float red[8];
    __shared__ float s_inv;
    if ((tid & 31) == 0) red[tid >> 5] = ssq;
    __syncthreads();
    if (tid == 0) {
        float tot = 0.f;
        #pragma unroll
        for (int w = 0; w < 8; ++w) tot += red[w];
        float nrm = fmaxf(sqrtf(tot), 1e-12f);
        s_inv = 1.0f / nrm;
    }
    __syncthreads();
    const float inv = s_inv;
    #pragma unroll
    for (int m = 0; m < 32; ++m)
        out[b * K_ * D_ + m * 256 + tid] = v[m] * inv;
}

extern "C" void kernel_launch(void* const* d_in, const int* in_sizes, int n_in,
                              void* d_out, int out_size) {
    const float* x    = (const float*)d_in[0];   // [32,4096,128] f32
    const float* cent = (const float*)d_in[1];   // [64,128] f32
    float* out = (float*)d_out;                  // [32,8192] f32
    (void)in_sizes; (void)n_in; (void)out_size;

    cudaFuncSetAttribute(vlad_main, cudaFuncAttributeMaxDynamicSharedMemorySize,
                         SMEM_FLOATS * (int)sizeof(float));

    vlad_zero<<<(B_ * K_ * D_ + 255) / 256, 256>>>();
    vlad_main<<<NCTA_, 256, SMEM_FLOATS * sizeof(float)>>>(x, cent);
    vlad_finalize<<<B_, 256>>>(cent, out);
}

// round 8
// speedup vs baseline: 1.1706x; 1.0087x over previous
#include <cuda_runtime.h>

// VLAD pooling: x [32,4096,128] f32, centroids [64,128] f32 -> out [32, 8192] f32
//
// R7: warp-local softmax (GEMM1 remapped so each point's 64 clusters live in
//     one warp -> register softmax, 3 syncs/tile instead of 4, no logits
//     smem round-trip); GEMM1 scalar FFMA (reg relief), GEMM2 packed fma2;
//     centroid smem gets its own swizzle for the stride-4-row read pattern.

#define B_      32
#define N_      4096
#define D_      128
#define K_      64
#define ALPHA_  100.0f
#define TILE_   64
#define NTILES_ (B_ * (N_ / TILE_))   // 2048 tiles total
#define NCTA_   296                   // 148 SMs * 2 CTAs
#define BASE_T  (NTILES_ / NCTA_)     // 6
#define EXTRA_T (NTILES_ - NCTA_ * BASE_T)  // 272

// shared memory layout (floats)
#define SM_CS 0                    // centroids [64][128], float4 col swizzled by (r>>2)&7
#define SM_C2 8192                 // c2 [64]
#define SM_XS 8256                 // x tile [64][128], float4 col swizzled by r&7
#define SM_X2 16448                // x2 [64]
#define SM_AS 16512                // softmax weights a [64][72] (stride 72)
#define A_STRIDE 72
#define SMEM_FLOATS (SM_AS + TILE_ * A_STRIDE)   // 21120 floats = 84480 B

__device__ float g_vlad[B_ * K_ * D_];
__device__ float g_asum[B_ * K_];

typedef unsigned long long u64t;

__device__ __forceinline__ void upk2(u64t v, float& lo, float& hi) {
    asm("mov.b64 {%0,%1}, %2;" : "=f"(lo), "=f"(hi) : "l"(v));
}
__device__ __forceinline__ u64t pk2(float lo, float hi) {
    u64t r; asm("mov.b64 %0, {%1,%2};" : "=l"(r) : "f"(lo), "f"(hi)); return r;
}
__device__ __forceinline__ u64t fma2(u64t a, u64t b, u64t c) {
    u64t d; asm("fma.rn.f32x2 %0, %1, %2, %3;" : "=l"(d) : "l"(a), "l"(b), "l"(c)); return d;
}

__global__ void vlad_zero() {
    int i = blockIdx.x * blockDim.x + threadIdx.x;
    if (i < B_ * K_ * D_) g_vlad[i] = 0.f;
    if (i < B_ * K_) g_asum[i] = 0.f;
}

__device__ __forceinline__ float dot4acc(float4 a, float4 b, float acc) {
    return fmaf(a.x, b.x, fmaf(a.y, b.y, fmaf(a.z, b.z, fmaf(a.w, b.w, acc))));
}

__global__ __launch_bounds__(256, 2)
void vlad_main(const float* __restrict__ x, const float* __restrict__ cent) {
    extern __shared__ float sm[];
    float* cs = sm + SM_CS;
    float* c2 = sm + SM_C2;
    float* xs = sm + SM_XS;
    float* x2 = sm + SM_X2;
    float* aw = sm + SM_AS;

    const int tid  = threadIdx.x;
    const int cta  = blockIdx.x;
    const int q    = tid & 3;      // quarter of a row for gmem loads
    const int r    = tid >> 2;     // row (point) for gmem loads, 0..63
    const int warp = tid >> 5;
    const int lane = tid & 31;

    // GEMM1 / softmax mapping: warp owns points 8w..8w+7
    const int pgrp = lane & 1;         // which half of the warp's 8 points
    const int kgrp = lane >> 1;        // cluster group 0..15 (4 clusters)
    const int p0   = warp * 8 + pgrp * 4;   // first of this lane's 4 points
    const int kc0  = kgrp * 4;              // first of this lane's 4 clusters
    const int xsw  = (pgrp * 4) & 7;        // xs swizzle base: (p0+i)&7 = xsw+i (i<4)
    const int csw  = kgrp & 7;              // cs swizzle for rows kc0..kc0+3

    // GEMM2 mapping (unchanged): 16 d-octets x 16 k-quads
    const int tn   = tid & 15;
    const int k0   = (tid >> 4) * 4;

    // chunked contiguous tile range for this CTA
    const int start = cta * BASE_T + (cta < EXTRA_T ? cta : EXTRA_T);
    const int cnt   = BASE_T + (cta < EXTRA_T ? 1 : 0);

    // ---- load centroids into smem (swizzled by (row>>2)&7) + c2 ----
    {
        const float4* c4 = (const float4*)cent;
        const int csz = (r >> 2) & 7;
        float csum = 0.f;
        #pragma unroll
        for (int it = 0; it < 8; ++it) {
            int f4 = q + it * 4;
            float4 v = c4[r * 32 + f4];
            ((float4*)(cs + r * 128))[f4 ^ csz] = v;
            csum = dot4acc(v, v, csum);
        }
        csum += __shfl_xor_sync(0xffffffffu, csum, 1);
        csum += __shfl_xor_sync(0xffffffffu, csum, 2);
        if (q == 0) c2[r] = csum;
    }
    __syncthreads();

    // per-lane centroid norms (constant across tiles)
    float c2v[4];
    #pragma unroll
    for (int j = 0; j < 4; ++j) c2v[j] = c2[kc0 + j];

    // persistent register accumulators
    u64t vl2[4][4];
    #pragma unroll
    for (int j = 0; j < 4; ++j)
        #pragma unroll
        for (int p = 0; p < 4; ++p) vl2[j][p] = 0ull;
    float asumr[4] = {0.f, 0.f, 0.f, 0.f};   // per-lane, clusters kc0..kc0+3
    int cur_b = start >> 6;

    for (int it = 0; it < cnt; ++it) {
        const int tg = start + it;
        const int b  = tg >> 6;
        const int t  = tg & 63;

        if (b != cur_b) {
            // flush register accumulators on batch change
            const int base = cur_b * K_ * D_;
            #pragma unroll
            for (int j = 0; j < 4; ++j)
                #pragma unroll
                for (int p = 0; p < 4; ++p) {
                    float lo, hi; upk2(vl2[j][p], lo, hi);
                    atomicAdd(&g_vlad[base + (k0 + j) * D_ + tn * 8 + 2 * p], lo);
                    atomicAdd(&g_vlad[base + (k0 + j) * D_ + tn * 8 + 2 * p + 1], hi);
                    vl2[j][p] = 0ull;
                }
            #pragma unroll
            for (int j = 0; j < 4; ++j) {
                atomicAdd(&g_asum[cur_b * K_ + kc0 + j], asumr[j]);
                asumr[j] = 0.f;
            }
            cur_b = b;
        }

        __syncthreads();  // previous tile's GEMM2 reads of xs/aw complete

        // ---- load x tile (float4 col swizzled by row&7) + x2 ----
        {
            const int rowg = b * N_ + t * TILE_ + r;
            const float4* x4 = (const float4*)x;
            const int xsz = r & 7;
            float xsum = 0.f;
            #pragma unroll
            for (int i8 = 0; i8 < 8; ++i8) {
                int f4 = q + i8 * 4;
                float4 v = x4[rowg * 32 + f4];
                ((float4*)(xs + r * 128))[f4 ^ xsz] = v;
                xsum = dot4acc(v, v, xsum);
            }
            xsum += __shfl_xor_sync(0xffffffffu, xsum, 1);
            xsum += __shfl_xor_sync(0xffffffffu, xsum, 2);
            if (q == 0) x2[r] = xsum;
        }
        __syncthreads();

        // ---- GEMM1 (scalar FFMA): 4 points {p0..p0+3} x 4 clusters {kc0..kc0+3} ----
        float acc[4][4];
        #pragma unroll
        for (int i = 0; i < 4; ++i)
            #pragma unroll
            for (int j = 0; j < 4; ++j) acc[i][j] = 0.f;

        #pragma unroll 4
        for (int d4 = 0; d4 < 32; ++d4) {
            float4 xv[4], cv[4];
            #pragma unroll
            for (int i = 0; i < 4; ++i)
                xv[i] = ((const float4*)(xs + (p0 + i) * 128))[d4 ^ ((xsw + i) & 7)];
            #pragma unroll
            for (int j = 0; j < 4; ++j)
                cv[j] = ((const float4*)(cs + (kc0 + j) * 128))[d4 ^ csw];
            #pragma unroll
            for (int i = 0; i < 4; ++i)
                #pragma unroll
                for (int j = 0; j < 4; ++j)
                    acc[i][j] = dot4acc(xv[i], cv[j], acc[i][j]);
        }

        // ---- logits + warp-local softmax (clusters of point p0+i live in the
        //      16 lanes sharing bit0; reduce via shfl_xor 2/4/8/16) ----
        #pragma unroll
        for (int i = 0; i < 4; ++i) {
            const float xx = x2[p0 + i];
            float lg[4];
            #pragma unroll
            for (int j = 0; j < 4; ++j) {
                float d2 = fmaxf(xx + c2v[j] - 2.f * acc[i][j], 0.f);
                lg[j] = -ALPHA_ * sqrtf(d2);
            }
            float m = fmaxf(fmaxf(lg[0], lg[1]), fmaxf(lg[2], lg[3]));
            #pragma unroll
            for (int o = 2; o <= 16; o <<= 1)
                m = fmaxf(m, __shfl_xor_sync(0xffffffffu, m, o));
            float e[4];
            float s = 0.f;
            #pragma unroll
            for (int j = 0; j < 4; ++j) { e[j] = __expf(lg[j] - m); s += e[j]; }
            #pragma unroll
            for (int o = 2; o <= 16; o <<= 1)
                s += __shfl_xor_sync(0xffffffffu, s, o);
            const float inv = 1.0f / s;
            float4 a4;
            a4.x = e[0] * inv; a4.y = e[1] * inv; a4.z = e[2] * inv; a4.w = e[3] * inv;
            asumr[0] += a4.x; asumr[1] += a4.y; asumr[2] += a4.z; asumr[3] += a4.w;
            *(float4*)(aw + (p0 + i) * A_STRIDE + kc0) = a4;
        }
        __syncthreads();

        // ---- GEMM2 (fma2): vl2[k0..k0+3][4 d-pairs @ d0=tn*8] += a[n][k] * x[n][d] ----
        #pragma unroll 4
        for (int n = 0; n < TILE_; ++n) {
            float4 av = *(const float4*)(aw + n * A_STRIDE + k0);
            const ulonglong2* xrow = (const ulonglong2*)(xs + n * 128);
            const int swz = n & 7;
            ulonglong2 xa = xrow[(2 * tn) ^ swz];       // logical d4 = 2*tn
            ulonglong2 xb = xrow[(2 * tn + 1) ^ swz];   // logical d4 = 2*tn+1
            u64t xp[4] = {xa.x, xa.y, xb.x, xb.y};
            u64t w2[4] = {pk2(av.x, av.x), pk2(av.y, av.y),
                          pk2(av.z, av.z), pk2(av.w, av.w)};
            #pragma unroll
            for (int j = 0; j < 4; ++j)
                #pragma unroll
                for (int p = 0; p < 4; ++p)
                    vl2[j][p] = fma2(w2[j], xp[p], vl2[j][p]);
        }
    }

    // ---- final flush of register accumulators ----
    const int base = cur_b * K_ * D_;
    #pragma unroll
    for (int j = 0; j < 4; ++j)
        #pragma unroll
        for (int p = 0; p < 4; ++p) {
            float lo, hi; upk2(vl2[j][p], lo, hi);
            atomicAdd(&g_vlad[base + (k0 + j) * D_ + tn * 8 + 2 * p], lo);
            atomicAdd(&g_vlad[base + (k0 + j) * D_ + tn * 8 + 2 * p + 1], hi);
        }
    #pragma unroll
    for (int j = 0; j < 4; ++j)
        atomicAdd(&g_asum[cur_b * K_ + kc0 + j], asumr[j]);
}

__global__ __launch_bounds__(256)
void vlad_finalize(const float* __restrict__ cent, float* __restrict__ out) {
    const int b = blockIdx.x;
    const int tid = threadIdx.x;
    float v[32];
    float ssq = 0.f;
    #pragma unroll
    for (int m = 0; m < 32; ++m) {
        const int e = m * 256 + tid;
        const int k = e >> 7;
        const int d = e & 127;
        float val = fmaf(-g_asum[b * K_ + k], cent[k * D_ + d], g_vlad[b * K_ * D_ + e]);
        v[m] = val;
        ssq = fmaf(val, val, ssq);
    }
    #pragma unroll
    for (int o = 16; o > 0; o >>= 1)
        ssq += __shfl_xor_sync(0xffffffffu, ssq, o);

    __shared__ float red[8];
    __shared__ float s_inv;
    if ((tid & 31) == 0) red[tid >> 5] = ssq;
    __syncthreads();
    if (tid == 0) {
        float tot = 0.f;
        #pragma unroll
        for (int w = 0; w < 8; ++w) tot += red[w];
        float nrm = fmaxf(sqrtf(tot), 1e-12f);
        s_inv = 1.0f / nrm;
    }
    __syncthreads();
    const float inv = s_inv;
    #pragma unroll
    for (int m = 0; m < 32; ++m)
        out[b * K_ * D_ + m * 256 + tid] = v[m] * inv;
}

extern "C" void kernel_launch(void* const* d_in, const int* in_sizes, int n_in,
                              void* d_out, int out_size) {
    const float* x    = (const float*)d_in[0];   // [32,4096,128] f32
    const float* cent = (const float*)d_in[1];   // [64,128] f32
    float* out = (float*)d_out;                  // [32,8192] f32
    (void)in_sizes; (void)n_in; (void)out_size;

    cudaFuncSetAttribute(vlad_main, cudaFuncAttributeMaxDynamicSharedMemorySize,
                         SMEM_FLOATS * (int)sizeof(float));

    vlad_zero<<<(B_ * K_ * D_ + 255) / 256, 256>>>();
    vlad_main<<<NCTA_, 256, SMEM_FLOATS * sizeof(float)>>>(x, cent);
    vlad_finalize<<<B_, 256>>>(cent, out);
}